// round 16
// baseline (speedup 1.0000x reference)
#include <cuda_runtime.h>
#include <cstdint>

// RadarSparseProcessor: out[v,o] = (sum_p sum_c x[v,p,c] * W[o,c]) / max(n_v, 1)
// V = 1048576, P = 4, C_IN = 4, C_OUT = 32. vnp is int32.
//
// R16: R12 structure (best: 35.36us) with 256-bit stores (st.global.v8.b32).
// Lane l stores channel-octet (l&3) of voxel 8k+(l>>2): one 1024 B
// contiguous STG.256 per warp per k -> 4 stores/tile instead of 8.
// Loads, butterfly reduce, smem park identical to R12.

#define THREADS 256
#define WARPS_PER_BLOCK (THREADS / 32)

__device__ __forceinline__ void st_v8(float* p, const float* f) {
    asm volatile("st.global.v8.b32 [%0], {%1,%2,%3,%4,%5,%6,%7,%8};"
                 :: "l"(p),
                    "r"(__float_as_uint(f[0])), "r"(__float_as_uint(f[1])),
                    "r"(__float_as_uint(f[2])), "r"(__float_as_uint(f[3])),
                    "r"(__float_as_uint(f[4])), "r"(__float_as_uint(f[5])),
                    "r"(__float_as_uint(f[6])), "r"(__float_as_uint(f[7]))
                 : "memory");
}

__global__ __launch_bounds__(THREADS, 4)
void radar_sparse_kernel(const float4* __restrict__ in4,  // [V*4] float4 (= [V,4,4])
                         const float4* __restrict__ W4,   // [32] float4 (= [32,4])
                         const int*    __restrict__ vnp,  // [V] int32
                         float4* __restrict__ out4,       // [V*8] float4 (= [V,32])
                         int V)
{
    __shared__ float4 sS[WARPS_PER_BLOCK][32];    // per-warp s-vector park

    const unsigned FULL = 0xFFFFFFFFu;
    const int lane  = threadIdx.x & 31;
    const int wwarp = threadIdx.x >> 5;
    const int gwarp = (blockIdx.x * blockDim.x + threadIdx.x) >> 5;
    const int vbase = gwarp * 32;                 // first voxel of this warp
    if (vbase >= V) return;

    // Channel octet o = lane&3 (channels 8o..8o+7): 8 W rows per lane.
    const int o = lane & 3;
    float4 wr[8];
    #pragma unroll
    for (int r = 0; r < 8; r++) wr[r] = W4[o * 8 + r];

    if (vbase + 32 <= V) {
        // ---------- fast path: full warp of 32 voxels ----------
        int n = __ldcs(vnp + vbase + lane);       // coalesced 128 B, evict-first
        float invl = 1.0f / (float)(n > 1 ? n : 1);

        // Front-batched streaming loads: 4x LDG.128.CS, contiguous 2048 B/warp.
        // Iter k, lane l holds point (l&3) of voxel 8k + (l>>2).
        const float4* inBase = in4 + (size_t)vbase * 4;
        float4 d[4];
        #pragma unroll
        for (int k = 0; k < 4; k++) d[k] = __ldcs(inBase + k * 32 + lane);

        float* outF = (float*)(out4 + (size_t)vbase * 8);

        #pragma unroll
        for (int k = 0; k < 4; k++) {
            // Butterfly sum over the point dimension (4-lane groups).
            float4 s = d[k];
            s.x += __shfl_xor_sync(FULL, s.x, 1);
            s.y += __shfl_xor_sync(FULL, s.y, 1);
            s.z += __shfl_xor_sync(FULL, s.z, 1);
            s.w += __shfl_xor_sync(FULL, s.w, 1);
            s.x += __shfl_xor_sync(FULL, s.x, 2);
            s.y += __shfl_xor_sync(FULL, s.y, 2);
            s.z += __shfl_xor_sync(FULL, s.z, 2);
            s.w += __shfl_xor_sync(FULL, s.w, 2);
            // Fold in 1/max(n,1) of voxel 8k + (l>>2).
            float ik = __shfl_sync(FULL, invl, 8 * k + (lane >> 2));
            s.x *= ik; s.y *= ik; s.z *= ik; s.w *= ik;
            // All 4 lanes of group j=(l>>2) hold s of voxel 8k+j.

            // Park s in smem: one lane per group writes -> 8 consecutive
            // float4s (128 B contiguous, conflict-free, 1 wavefront).
            if ((lane & 3) == 0) sS[wwarp][8 * k + (lane >> 2)] = s;
            __syncwarp();

            // ONE 256-bit store iteration per k: warp covers voxels 8k..8k+7
            // (8 x 128 B = 1024 B contiguous). Lane l -> voxel 8k+(l>>2),
            // octet o = l&3 (channels 8o..8o+7).
            {
                const int vloc = 8 * k + (lane >> 2);
                float4 sv = sS[wwarp][vloc];           // 4-way bcast LDS.128
                float f[8];
                #pragma unroll
                for (int r = 0; r < 8; r++) {
                    f[r] = fmaf(wr[r].x, sv.x,
                           fmaf(wr[r].y, sv.y,
                           fmaf(wr[r].z, sv.z, wr[r].w * sv.w)));
                }
                st_v8(outF + vloc * 32 + o * 8, f);    // 1024 B contiguous/warp
            }
            __syncwarp();
        }
    } else {
        // ---------- tail path: per-lane scalar (absent for V = 1M) ----------
        int v = vbase + lane;
        if (v < V) {
            const float4* vrow = in4 + (size_t)v * 4;
            float4 p0 = vrow[0], p1 = vrow[1], p2 = vrow[2], p3 = vrow[3];
            int n = vnp[v];
            float inv = 1.0f / (float)(n > 1 ? n : 1);
            float sx = ((p0.x + p1.x) + (p2.x + p3.x)) * inv;
            float sy = ((p0.y + p1.y) + (p2.y + p3.y)) * inv;
            float sz = ((p0.z + p1.z) + (p2.z + p3.z)) * inv;
            float sw = ((p0.w + p1.w) + (p2.w + p3.w)) * inv;
            float4* orow = out4 + (size_t)v * 8;
            #pragma unroll
            for (int kk = 0; kk < 8; kk++) {
                float4 a = W4[kk * 4 + 0], b = W4[kk * 4 + 1];
                float4 c = W4[kk * 4 + 2], e = W4[kk * 4 + 3];
                float4 ov;
                ov.x = fmaf(a.x, sx, fmaf(a.y, sy, fmaf(a.z, sz, a.w * sw)));
                ov.y = fmaf(b.x, sx, fmaf(b.y, sy, fmaf(b.z, sz, b.w * sw)));
                ov.z = fmaf(c.x, sx, fmaf(c.y, sy, fmaf(c.z, sz, c.w * sw)));
                ov.w = fmaf(e.x, sx, fmaf(e.y, sy, fmaf(e.z, sz, e.w * sw)));
                orow[kk] = ov;
            }
        }
    }
}

extern "C" void kernel_launch(void* const* d_in, const int* in_sizes, int n_in,
                              void* d_out, int out_size)
{
    const float4* in4 = (const float4*)d_in[0];   // voxel_features [V,4,4] f32
    const float4* W4  = (const float4*)d_in[1];   // W [32,4] f32
    const int*    vnp = (const int*)d_in[2];      // voxel_num_points [V] i32
    float4*       out = (float4*)d_out;           // [V,32] f32

    int V = in_sizes[2];
    int warps = (V + 31) / 32;
    int blocks = (warps * 32 + THREADS - 1) / THREADS;
    radar_sparse_kernel<<<blocks, THREADS>>>(in4, W4, vnp, out, V);
}

// round 17
// speedup vs baseline: 1.1223x; 1.1223x over previous
#include <cuda_runtime.h>

// RadarSparseProcessor: out[v,o] = (sum_p sum_c x[v,p,c] * W[o,c]) / max(n_v, 1)
// V = 1048576, P = 4, C_IN = 4, C_OUT = 32. vnp is int32.
//
// FINAL (= R12, best measured: 35.36 us, kernel 31.36 us, DRAM 59%).
// Warp-autonomous: coalesced LDG.128.CS loads (evict-first; keeps the
// single-use read stream from displacing L2-resident output), shfl.xor
// butterfly point-reduction with 1/max(n,1) folded in, per-warp smem park
// (conflict-free STS.128 + broadcast LDS.128), plain write-back STG.128
// stores (contiguous 512 B/warp; ~60 MB/replay absorbed in L2).
// Session evidence: 9 structural variants (smem-staged, TMA bulk, 2xMLP,
// persistent+prefetch, evict_last, STG.256, occupancy sweeps) all land at
// or above this point — this is the DRAM-side equilibrium for the 1:2
// read:write mix on GB300.

#define THREADS 256
#define WARPS_PER_BLOCK (THREADS / 32)

__global__ __launch_bounds__(THREADS, 5)
void radar_sparse_kernel(const float4* __restrict__ in4,  // [V*4] float4 (= [V,4,4])
                         const float4* __restrict__ W4,   // [32] float4 (= [32,4])
                         const int*    __restrict__ vnp,  // [V] int32
                         float4* __restrict__ out4,       // [V*8] float4 (= [V,32])
                         int V)
{
    __shared__ float4 sS[WARPS_PER_BLOCK][32];    // per-warp s-vector park

    const unsigned FULL = 0xFFFFFFFFu;
    const int lane  = threadIdx.x & 31;
    const int wwarp = threadIdx.x >> 5;
    const int gwarp = (blockIdx.x * blockDim.x + threadIdx.x) >> 5;
    const int vbase = gwarp * 32;                 // first voxel of this warp
    if (vbase >= V) return;

    // Weight rows for this lane's channel quad q = lane&7 (channels 4q..4q+3).
    const int q = lane & 7;
    const float4 w0 = W4[q * 4 + 0];
    const float4 w1 = W4[q * 4 + 1];
    const float4 w2 = W4[q * 4 + 2];
    const float4 w3 = W4[q * 4 + 3];

    if (vbase + 32 <= V) {
        // ---------- fast path: full warp of 32 voxels ----------
        int n = __ldcs(vnp + vbase + lane);       // coalesced 128 B, streaming
        float invl = 1.0f / (float)(n > 1 ? n : 1);

        // Front-batched streaming loads: 4x LDG.128.CS, contiguous 2048 B/warp.
        // Iter k, lane l holds point (l&3) of voxel 8k + (l>>2).
        const float4* inBase = in4 + (size_t)vbase * 4;
        float4 d[4];
        #pragma unroll
        for (int k = 0; k < 4; k++) d[k] = __ldcs(inBase + k * 32 + lane);

        float4* outBase = out4 + (size_t)vbase * 8;

        #pragma unroll
        for (int k = 0; k < 4; k++) {
            // Butterfly sum over the point dimension (4-lane groups).
            float4 s = d[k];
            s.x += __shfl_xor_sync(FULL, s.x, 1);
            s.y += __shfl_xor_sync(FULL, s.y, 1);
            s.z += __shfl_xor_sync(FULL, s.z, 1);
            s.w += __shfl_xor_sync(FULL, s.w, 1);
            s.x += __shfl_xor_sync(FULL, s.x, 2);
            s.y += __shfl_xor_sync(FULL, s.y, 2);
            s.z += __shfl_xor_sync(FULL, s.z, 2);
            s.w += __shfl_xor_sync(FULL, s.w, 2);
            // Fold in 1/max(n,1) of voxel 8k + (l>>2).
            float ik = __shfl_sync(FULL, invl, 8 * k + (lane >> 2));
            s.x *= ik; s.y *= ik; s.z *= ik; s.w *= ik;
            // All 4 lanes of group j=(l>>2) hold s of voxel 8k+j.

            // Park s in smem: one lane per group writes -> 8 consecutive
            // float4s (128 B contiguous, conflict-free, 1 wavefront).
            if ((lane & 3) == 0) sS[wwarp][8 * k + (lane >> 2)] = s;
            __syncwarp();

            // Store iterations i = 2k, 2k+1; iter i covers voxels 4i..4i+3.
            // Lane l writes voxel 4i+(l>>3), channel quad q.
            #pragma unroll
            for (int h = 0; h < 2; h++) {
                const int i = 2 * k + h;
                float4 sv = sS[wwarp][4 * i + (lane >> 3)];  // 8-way bcast LDS.128
                float4 o;
                o.x = fmaf(w0.x, sv.x, fmaf(w0.y, sv.y, fmaf(w0.z, sv.z, w0.w * sv.w)));
                o.y = fmaf(w1.x, sv.x, fmaf(w1.y, sv.y, fmaf(w1.z, sv.z, w1.w * sv.w)));
                o.z = fmaf(w2.x, sv.x, fmaf(w2.y, sv.y, fmaf(w2.z, sv.z, w2.w * sv.w)));
                o.w = fmaf(w3.x, sv.x, fmaf(w3.y, sv.y, fmaf(w3.z, sv.z, w3.w * sv.w)));
                outBase[i * 32 + lane] = o;   // plain write-back store -> L2-resident
            }
            __syncwarp();
        }
    } else {
        // ---------- tail path: per-lane scalar (absent for V = 1M) ----------
        int v = vbase + lane;
        if (v < V) {
            const float4* vrow = in4 + (size_t)v * 4;
            float4 p0 = vrow[0], p1 = vrow[1], p2 = vrow[2], p3 = vrow[3];
            int n = vnp[v];
            float inv = 1.0f / (float)(n > 1 ? n : 1);
            float sx = ((p0.x + p1.x) + (p2.x + p3.x)) * inv;
            float sy = ((p0.y + p1.y) + (p2.y + p3.y)) * inv;
            float sz = ((p0.z + p1.z) + (p2.z + p3.z)) * inv;
            float sw = ((p0.w + p1.w) + (p2.w + p3.w)) * inv;
            float4* orow = out4 + (size_t)v * 8;
            #pragma unroll
            for (int kk = 0; kk < 8; kk++) {
                float4 a = W4[kk * 4 + 0], b = W4[kk * 4 + 1];
                float4 c = W4[kk * 4 + 2], e = W4[kk * 4 + 3];
                float4 o;
                o.x = fmaf(a.x, sx, fmaf(a.y, sy, fmaf(a.z, sz, a.w * sw)));
                o.y = fmaf(b.x, sx, fmaf(b.y, sy, fmaf(b.z, sz, b.w * sw)));
                o.z = fmaf(c.x, sx, fmaf(c.y, sy, fmaf(c.z, sz, c.w * sw)));
                o.w = fmaf(e.x, sx, fmaf(e.y, sy, fmaf(e.z, sz, e.w * sw)));
                orow[kk] = o;
            }
        }
    }
}

extern "C" void kernel_launch(void* const* d_in, const int* in_sizes, int n_in,
                              void* d_out, int out_size)
{
    const float4* in4 = (const float4*)d_in[0];   // voxel_features [V,4,4] f32
    const float4* W4  = (const float4*)d_in[1];   // W [32,4] f32
    const int*    vnp = (const int*)d_in[2];      // voxel_num_points [V] i32
    float4*       out = (float4*)d_out;           // [V,32] f32

    int V = in_sizes[2];
    int warps = (V + 31) / 32;
    int blocks = (warps * 32 + THREADS - 1) / THREADS;
    radar_sparse_kernel<<<blocks, THREADS>>>(in4, W4, vnp, out, V);
}